// round 9
// baseline (speedup 1.0000x reference)
#include <cuda_runtime.h>

#define NLAT 360
#define NLON 720
#define LMAX 360
#define MMAX 361
#define NB   256                   // B*C

#define X_ELEMS  66355200u         // 256*360*720
#define W_ELEMS  46785600u         // 361*360*360
#define OUT_ELEMS 33269760u        // 256*360*361 floats (real part)

// Intermediate real spectrum, layout [m][k][bc] (bc contiguous)
__device__ __align__(256) float g_X2[(size_t)MMAX * NLAT * NB];

__global__ void zero_out(float* outf, unsigned capF) {
    unsigned i = blockIdx.x * blockDim.x + threadIdx.x;
    if (i < capF) outf[i] = 0.f;
}

// ---------------------------------------------------------------------------
// Stage A (independent impl): one block per input row r=(bc,k).
// X2[m][k][bc] = SC * sum_n x[r][n] * cos(2*pi*n*m/720)
// Cos table (720 entries, SC folded) and x row live in shared.
// Each thread handles m = t, t+128, t+256 with exact integer phase stepping.
// ---------------------------------------------------------------------------
__global__ __launch_bounds__(128) void dft_simple(const float* __restrict__ x) {
    __shared__ float xs[NLON];
    __shared__ float ct[NLON];

    int r  = blockIdx.x;               // 0..92159
    int bc = r / NLAT;
    int k  = r - bc * NLAT;
    int t  = threadIdx.x;

    const float SC = 8.7266462599716478846e-3f;   // 2*pi/720
    for (int j = t; j < NLON; j += 128) {
        xs[j] = x[(size_t)r * NLON + j];
        ct[j] = SC * cospif((float)j * (1.0f / 360.0f));  // cos(pi*j/360)
    }
    __syncthreads();

    int m1 = t;              // < 128
    int m2 = t + 128;        // < 256
    int m3 = t + 256;        // < 384 (valid iff < 361)
    float a1 = 0.f, a2 = 0.f, a3 = 0.f;
    int i1 = 0, i2 = 0, i3 = 0;

#pragma unroll 4
    for (int n = 0; n < NLON; n++) {
        float xv = xs[n];
        a1 += xv * ct[i1];
        a2 += xv * ct[i2];
        a3 += xv * ct[i3];
        i1 += m1; if (i1 >= NLON) i1 -= NLON;
        i2 += m2; if (i2 >= NLON) i2 -= NLON;
        i3 += m3; if (i3 >= NLON) i3 -= NLON;
    }

    g_X2[((size_t)m1 * NLAT + k) * NB + bc] = a1;
    g_X2[((size_t)m2 * NLAT + k) * NB + bc] = a2;
    if (m3 < MMAX)
        g_X2[((size_t)m3 * NLAT + k) * NB + bc] = a3;
}

// ---------------------------------------------------------------------------
// Stage B (independent impl): one block per (m, 8-l strip); 256 threads = bc.
// out[bc,l,m] = sum_k X2[m][k][bc] * w[m,l,k]
// w strip [8][360] in shared; X2 loads coalesced across bc.
// Triangle: strip entirely below m -> zeros.
// ---------------------------------------------------------------------------
__global__ __launch_bounds__(256) void leg_simple(const float* __restrict__ w,
                                                  float* __restrict__ outf,
                                                  unsigned capF) {
    __shared__ float sW[8 * NLAT];

    int l0 = blockIdx.x * 8;           // 0,8,...,352  (360/8 = 45 exact)
    int m  = blockIdx.y;               // 0..360
    int t  = threadIdx.x;              // bc

    float acc[8];
#pragma unroll
    for (int j = 0; j < 8; j++) acc[j] = 0.f;

    if (m <= l0 + 7) {                 // strip has some l >= m
        const float* wS = w + (size_t)m * (LMAX * NLAT) + (size_t)l0 * NLAT;
        for (int idx = t; idx < 8 * NLAT; idx += 256)
            sW[idx] = wS[idx];
        __syncthreads();

        const float* Xm = g_X2 + (size_t)m * NLAT * NB;
        for (int k = 0; k < NLAT; k++) {
            float xv = Xm[(size_t)k * NB + t];
#pragma unroll
            for (int j = 0; j < 8; j++)
                acc[j] += xv * sW[j * NLAT + k];
        }
    }

#pragma unroll
    for (int j = 0; j < 8; j++) {
        unsigned oi = ((unsigned)t * LMAX + (unsigned)(l0 + j)) * MMAX + (unsigned)m;
        if (oi < capF) outf[oi] = acc[j];
    }
}

// ---------------------------------------------------------------------------
extern "C" void kernel_launch(void* const* d_in, const int* in_sizes, int n_in,
                              void* d_out, int out_size) {
    const float* x = nullptr;
    const float* w = nullptr;
    for (int i = 0; i < n_in; i++) {
        long s = in_sizes[i];
        if (s == (long)X_ELEMS || s == (long)X_ELEMS * 4) x = (const float*)d_in[i];
        else if (s == (long)W_ELEMS || s == (long)W_ELEMS * 4) w = (const float*)d_in[i];
    }
    float* outf = (float*)d_out;

    long cf = (long)out_size;
    if (cf < 0) cf = 0;
    if (cf > (long)OUT_ELEMS) cf = (long)OUT_ELEMS;
    unsigned capF = (unsigned)cf;

    if (!x || !w) {
        zero_out<<<(capF + 255) / 256, 256>>>(outf, capF);
        return;
    }

    dft_simple<<<NB * NLAT, 128>>>(x);                 // 92160 blocks

    dim3 gB(LMAX / 8, MMAX);                           // 45 x 361
    leg_simple<<<gB, 256>>>(w, outf, capF);
}

// round 10
// speedup vs baseline: 6.9076x; 6.9076x over previous
#include <cuda_runtime.h>

#define NLAT 360
#define NLON 720
#define LMAX 360
#define MMAX 361
#define NB   256                   // B*C
#define NROWS (NB * NLAT)          // 92160
#define KF   368                   // folded K (361 padded to 23*16)
#define FPAD 384                   // padded MMAX for table rows

#define X_ELEMS  66355200u         // 256*360*720
#define W_ELEMS  46785600u         // 361*360*360
#define OUT_ELEMS 33269760u        // 256*360*361 floats (real part)

// Folded cosine table: g_Ft[n][m], n<KF, m<FPAD.
//   n<=360, m<=360 : SC*cos(2*pi*n*m/720) * (0.5 if n==0 or n==360)
//   else 0
__device__ __align__(256) float g_Ft[KF * FPAD];
// Intermediate real spectrum, layout [m][r'], r' = k*NB + bc  (== [m][k][bc])
__device__ __align__(256) float g_X2[(size_t)MMAX * NROWS];

// ---------------------------------------------------------------------------
__global__ void init_tables() {
    unsigned idx = blockIdx.x * blockDim.x + threadIdx.x;
    if (idx >= KF * FPAD) return;
    unsigned n = idx / FPAD;
    unsigned m = idx - n * FPAD;
    float v = 0.f;
    if (n <= 360u && m < MMAX) {
        unsigned r = (n * m) % NLON;       // angle = pi * r / 360
        double s, c;
        sincospi((double)r / 360.0, &s, &c);
        double SC = 6.283185307179586476925286766559 / 720.0;
        if (n == 0u || n == 360u) SC *= 0.5;
        v = (float)(SC * c);
    }
    g_Ft[idx] = v;
}

__global__ void zero_out(float* outf, unsigned capF) {
    unsigned i = blockIdx.x * blockDim.x + threadIdx.x;
    if (i < capF) outf[i] = 0.f;
}

// ---------------------------------------------------------------------------
// Stage A: X2[m][r'] = sum_{n=0}^{367} (x[bc,k,n] + x[bc,k,(720-n)%720]) * Ft[n][m]
// r' = k*256 + bc  (bc = r' & 255, k = r' >> 8; 64-row tile => fixed k).
// 64(r') x 64(m) tile, K=368 in 23 steps of 16.
// ---------------------------------------------------------------------------
__global__ __launch_bounds__(256) void dft_gemm(const float* __restrict__ x) {
    __shared__ __align__(16) float As[16][64];
    __shared__ __align__(16) float Bc[16][64];

    unsigned tid = threadIdx.x;
    unsigned tx = tid & 15u, ty = tid >> 4;
    unsigned m0 = blockIdx.x << 6;
    unsigned r0 = blockIdx.y << 6;

    unsigned aI = tid >> 2;            // tile row (0..63)
    unsigned aK = (tid & 3u) << 2;     // n offset (0,4,8,12)
    unsigned bM = tx << 2;             // table col offset, row = ty

    float acc[4][4];
#pragma unroll
    for (int i = 0; i < 4; i++)
#pragma unroll
        for (int j = 0; j < 4; j++) acc[i][j] = 0.f;

    unsigned rp = r0 + aI;             // r' of this thread's A row
    unsigned bc = rp & 255u;
    unsigned k  = rp >> 8;             // same k for whole block
    const float* xRow = x + ((size_t)bc * NLAT + k) * NLON;

    for (unsigned kt = 0; kt < KF; kt += 16) {
        unsigned n0 = kt + aK;                      // multiple of 4, <= 364
        float4 a4 = *(const float4*)(xRow + n0);    // x[n0..n0+3]
        float fold[4];
#pragma unroll
        for (unsigned c = 0; c < 4; c++) {
            unsigned n = n0 + c;                    // <= 367
            unsigned n2 = (NLON - n) & 719u;        // (720-n)%720 (720=2^4*45; use cond)
            n2 = (n == 0u) ? 0u : (NLON - n);
            fold[c] = __ldg(xRow + n2);
        }
        float4 f4 = *(const float4*)(g_Ft + (kt + ty) * FPAD + m0 + bM);
        __syncthreads();
        As[aK + 0][aI] = a4.x + fold[0];
        As[aK + 1][aI] = a4.y + fold[1];
        As[aK + 2][aI] = a4.z + fold[2];
        As[aK + 3][aI] = a4.w + fold[3];
        *(float4*)&Bc[ty][bM] = f4;
        __syncthreads();
#pragma unroll
        for (unsigned kk = 0; kk < 16; kk++) {
            float4 av = *(float4*)&As[kk][tx << 2];
            float4 bv = *(float4*)&Bc[kk][ty << 2];
            float aa[4] = {av.x, av.y, av.z, av.w};
            float bb[4] = {bv.x, bv.y, bv.z, bv.w};
#pragma unroll
            for (int i = 0; i < 4; i++)
#pragma unroll
                for (int j = 0; j < 4; j++)
                    acc[i][j] += aa[i] * bb[j];
        }
    }

    // Store: X2[m][r'] with r' contiguous -> coalesced float4
    unsigned rbase = r0 + (tx << 2);
#pragma unroll
    for (unsigned j = 0; j < 4; j++) {
        unsigned m = m0 + (ty << 2) + j;
        if (m < MMAX) {
            float4 v = make_float4(acc[0][j], acc[1][j], acc[2][j], acc[3][j]);
            *(float4*)(g_X2 + (size_t)m * NROWS + rbase) = v;
        }
    }
}

// ---------------------------------------------------------------------------
// Stage B (UNCHANGED from verified R9): one block per (m, 8-l strip).
// out[bc,l,m] = sum_k X2[m][k][bc] * w[m,l,k]
// ---------------------------------------------------------------------------
__global__ __launch_bounds__(256) void leg_simple(const float* __restrict__ w,
                                                  float* __restrict__ outf,
                                                  unsigned capF) {
    __shared__ float sW[8 * NLAT];

    int l0 = blockIdx.x * 8;           // 0,8,...,352
    int m  = blockIdx.y;               // 0..360
    int t  = threadIdx.x;              // bc

    float acc[8];
#pragma unroll
    for (int j = 0; j < 8; j++) acc[j] = 0.f;

    if (m <= l0 + 7) {
        const float* wS = w + (size_t)m * (LMAX * NLAT) + (size_t)l0 * NLAT;
        for (int idx = t; idx < 8 * NLAT; idx += 256)
            sW[idx] = wS[idx];
        __syncthreads();

        const float* Xm = g_X2 + (size_t)m * NLAT * NB;
        for (int k = 0; k < NLAT; k++) {
            float xv = Xm[(size_t)k * NB + t];
#pragma unroll
            for (int j = 0; j < 8; j++)
                acc[j] += xv * sW[j * NLAT + k];
        }
    }

#pragma unroll
    for (int j = 0; j < 8; j++) {
        unsigned oi = ((unsigned)t * LMAX + (unsigned)(l0 + j)) * MMAX + (unsigned)m;
        if (oi < capF) outf[oi] = acc[j];
    }
}

// ---------------------------------------------------------------------------
extern "C" void kernel_launch(void* const* d_in, const int* in_sizes, int n_in,
                              void* d_out, int out_size) {
    const float* x = nullptr;
    const float* w = nullptr;
    for (int i = 0; i < n_in; i++) {
        long s = in_sizes[i];
        if (s == (long)X_ELEMS || s == (long)X_ELEMS * 4) x = (const float*)d_in[i];
        else if (s == (long)W_ELEMS || s == (long)W_ELEMS * 4) w = (const float*)d_in[i];
    }
    float* outf = (float*)d_out;

    long cf = (long)out_size;
    if (cf < 0) cf = 0;
    if (cf > (long)OUT_ELEMS) cf = (long)OUT_ELEMS;
    unsigned capF = (unsigned)cf;

    if (!x || !w) {
        zero_out<<<(capF + 255) / 256, 256>>>(outf, capF);
        return;
    }

    init_tables<<<(KF * FPAD + 255) / 256, 256>>>();

    dim3 gA((MMAX + 63) / 64, NROWS / 64);          // 6 x 1440
    dft_gemm<<<gA, 256>>>(x);

    dim3 gB(LMAX / 8, MMAX);                        // 45 x 361
    leg_simple<<<gB, 256>>>(w, outf, capF);
}

// round 11
// speedup vs baseline: 7.8239x; 1.1327x over previous
#include <cuda_runtime.h>

#define NLAT 360
#define NLON 720
#define LMAX 360
#define MMAX 361
#define NB   256                   // B*C
#define NROWS (NB * NLAT)          // 92160
#define KF   368                   // folded K for stage A (23*16)
#define FPAD 384                   // padded MMAX for table rows
#define KBF  192                   // folded K for stage B (12*16), valid k<180

#define X_ELEMS  66355200u         // 256*360*720
#define W_ELEMS  46785600u         // 361*360*360
#define OUT_ELEMS 33269760u        // 256*360*361 floats (real part)

// Folded cosine table: g_Ft[n][m]
__device__ __align__(256) float g_Ft[KF * FPAD];
// Intermediate real spectrum, layout [m][r'], r' = k*NB + bc  (== [m][k][bc])
__device__ __align__(256) float g_X2[(size_t)MMAX * NROWS];

// ---------------------------------------------------------------------------
__global__ void init_tables() {
    unsigned idx = blockIdx.x * blockDim.x + threadIdx.x;
    if (idx >= KF * FPAD) return;
    unsigned n = idx / FPAD;
    unsigned m = idx - n * FPAD;
    float v = 0.f;
    if (n <= 360u && m < MMAX) {
        unsigned r = (n * m) % NLON;       // angle = pi * r / 360
        double s, c;
        sincospi((double)r / 360.0, &s, &c);
        double SC = 6.283185307179586476925286766559 / 720.0;
        if (n == 0u || n == 360u) SC *= 0.5;
        v = (float)(SC * c);
    }
    g_Ft[idx] = v;
}

__global__ void zero_out(float* outf, unsigned capF) {
    unsigned i = blockIdx.x * blockDim.x + threadIdx.x;
    if (i < capF) outf[i] = 0.f;
}

// ---------------------------------------------------------------------------
// Stage A (UNCHANGED, verified R10):
// X2[m][r'] = sum_{n<368} (x[bc,k,n] + x[bc,k,(720-n)%720]) * Ft[n][m]
// ---------------------------------------------------------------------------
__global__ __launch_bounds__(256) void dft_gemm(const float* __restrict__ x) {
    __shared__ __align__(16) float As[16][64];
    __shared__ __align__(16) float Bc[16][64];

    unsigned tid = threadIdx.x;
    unsigned tx = tid & 15u, ty = tid >> 4;
    unsigned m0 = blockIdx.x << 6;
    unsigned r0 = blockIdx.y << 6;

    unsigned aI = tid >> 2;
    unsigned aK = (tid & 3u) << 2;
    unsigned bM = tx << 2;

    float acc[4][4];
#pragma unroll
    for (int i = 0; i < 4; i++)
#pragma unroll
        for (int j = 0; j < 4; j++) acc[i][j] = 0.f;

    unsigned rp = r0 + aI;
    unsigned bc = rp & 255u;
    unsigned k  = rp >> 8;
    const float* xRow = x + ((size_t)bc * NLAT + k) * NLON;

    for (unsigned kt = 0; kt < KF; kt += 16) {
        unsigned n0 = kt + aK;
        float4 a4 = *(const float4*)(xRow + n0);
        float fold[4];
#pragma unroll
        for (unsigned c = 0; c < 4; c++) {
            unsigned n = n0 + c;
            unsigned n2 = (n == 0u) ? 0u : (NLON - n);
            fold[c] = __ldg(xRow + n2);
        }
        float4 f4 = *(const float4*)(g_Ft + (kt + ty) * FPAD + m0 + bM);
        __syncthreads();
        As[aK + 0][aI] = a4.x + fold[0];
        As[aK + 1][aI] = a4.y + fold[1];
        As[aK + 2][aI] = a4.z + fold[2];
        As[aK + 3][aI] = a4.w + fold[3];
        *(float4*)&Bc[ty][bM] = f4;
        __syncthreads();
#pragma unroll
        for (unsigned kk = 0; kk < 16; kk++) {
            float4 av = *(float4*)&As[kk][tx << 2];
            float4 bv = *(float4*)&Bc[kk][ty << 2];
            float aa[4] = {av.x, av.y, av.z, av.w};
            float bb[4] = {bv.x, bv.y, bv.z, bv.w};
#pragma unroll
            for (int i = 0; i < 4; i++)
#pragma unroll
                for (int j = 0; j < 4; j++)
                    acc[i][j] += aa[i] * bb[j];
        }
    }

    unsigned rbase = r0 + (tx << 2);
#pragma unroll
    for (unsigned j = 0; j < 4; j++) {
        unsigned m = m0 + (ty << 2) + j;
        if (m < MMAX) {
            float4 v = make_float4(acc[0][j], acc[1][j], acc[2][j], acc[3][j]);
            *(float4*)(g_X2 + (size_t)m * NROWS + rbase) = v;
        }
    }
}

// ---------------------------------------------------------------------------
// Stage B v2: GEMM 64(bc) x 64(l) per m, K folded by Legendre parity:
//   weights[m,l,359-k] = (-1)^(l+m) * weights[m,l,k]
//   out[bc,l,m] = sum_{k<180} w[m,l,k] * ( X[k]+X[359-k]  if (l+m) even
//                                          X[k]-X[359-k]  if (l+m) odd  )
// K padded 180 -> 192 (12 tiles of 16); k>=180 zeroed in A tiles.
// Parity selection: block-uniform pointer swap on (m&1), alternate by frag j.
// Triangle: tile skipped (zeros) when m > l0+63.
// ---------------------------------------------------------------------------
__global__ __launch_bounds__(256) void leg_gemm(const float* __restrict__ w,
                                                float* __restrict__ outf,
                                                unsigned capF) {
    unsigned m   = blockIdx.z;             // 0..360
    unsigned l0  = blockIdx.x << 6;        // 0,64,...,320
    unsigned bc0 = blockIdx.y << 6;        // 0,64,128,192
    unsigned tid = threadIdx.x;
    unsigned tx = tid & 15u, ty = tid >> 4;

    float acc[4][4];
#pragma unroll
    for (int i = 0; i < 4; i++)
#pragma unroll
        for (int j = 0; j < 4; j++) acc[i][j] = 0.f;

    if (m <= l0 + 63u) {
        __shared__ __align__(16) float Ae[16][64];
        __shared__ __align__(16) float Ao[16][64];
        __shared__ __align__(16) float Bw[16][64];

        unsigned kk = tid >> 4;            // k row for A loads (0..15)
        unsigned b4 = (tid & 15u) << 2;    // bc offset (float4)
        unsigned lw = tid >> 2;            // l for w loads (0..63)
        unsigned kw = (tid & 3u) << 2;     // k offset for w loads
        bool lvalid = (l0 + lw) < LMAX;

        const float* Xm = g_X2 + (size_t)m * NROWS;
        const float* wL = w + (size_t)m * (LMAX * NLAT) + (size_t)(l0 + lw) * NLAT;

        // parity: even (l+m) uses Xe, odd uses Xo.  l = l0 + ty*4 + j,
        // l0 and ty*4 even => parity = (j + m) & 1, uniform in block given j.
        const float (*Aev)[64];
        const float (*Aod)[64];

        for (unsigned k0 = 0; k0 < KBF; k0 += 16) {
            float4 e4, o4;
            unsigned kg = k0 + kk;
            if (kg < 180u) {
                float4 f = *(const float4*)(Xm + (size_t)kg * NB + bc0 + b4);
                float4 r = *(const float4*)(Xm + (size_t)(359u - kg) * NB + bc0 + b4);
                e4 = make_float4(f.x + r.x, f.y + r.y, f.z + r.z, f.w + r.w);
                o4 = make_float4(f.x - r.x, f.y - r.y, f.z - r.z, f.w - r.w);
            } else {
                e4 = make_float4(0.f, 0.f, 0.f, 0.f);
                o4 = e4;
            }
            // w[m][l0+lw][k0+kw .. +3]  (k0+kw+3 <= 191 < 360, always in-range)
            float4 w4 = lvalid ? *(const float4*)(wL + k0 + kw)
                               : make_float4(0.f, 0.f, 0.f, 0.f);
            __syncthreads();
            *(float4*)&Ae[kk][b4] = e4;
            *(float4*)&Ao[kk][b4] = o4;
            Bw[kw + 0][lw] = w4.x;
            Bw[kw + 1][lw] = w4.y;
            Bw[kw + 2][lw] = w4.z;
            Bw[kw + 3][lw] = w4.w;
            __syncthreads();

            Aev = (m & 1u) ? Ao : Ae;      // source for even j
            Aod = (m & 1u) ? Ae : Ao;      // source for odd j
#pragma unroll
            for (unsigned k = 0; k < 16; k++) {
                float4 ea = *(const float4*)&Aev[k][tx << 2];
                float4 oa = *(const float4*)&Aod[k][tx << 2];
                float4 wv = *(const float4*)&Bw[k][ty << 2];
                float ee[4] = {ea.x, ea.y, ea.z, ea.w};
                float oo[4] = {oa.x, oa.y, oa.z, oa.w};
#pragma unroll
                for (int i = 0; i < 4; i++) {
                    acc[i][0] += ee[i] * wv.x;   // j=0 even
                    acc[i][1] += oo[i] * wv.y;   // j=1 odd
                    acc[i][2] += ee[i] * wv.z;   // j=2 even
                    acc[i][3] += oo[i] * wv.w;   // j=3 odd
                }
            }
        }
    }

    // Stores: out[bc][l][m], scalar, guarded (zeros for skipped tiles)
#pragma unroll
    for (unsigned i = 0; i < 4; i++) {
        unsigned bc = bc0 + (tx << 2) + i;
#pragma unroll
        for (unsigned j = 0; j < 4; j++) {
            unsigned l = l0 + (ty << 2) + j;
            if (l < LMAX) {
                unsigned oi = (bc * LMAX + l) * MMAX + m;
                if (oi < capF) outf[oi] = acc[i][j];
            }
        }
    }
}

// ---------------------------------------------------------------------------
extern "C" void kernel_launch(void* const* d_in, const int* in_sizes, int n_in,
                              void* d_out, int out_size) {
    const float* x = nullptr;
    const float* w = nullptr;
    for (int i = 0; i < n_in; i++) {
        long s = in_sizes[i];
        if (s == (long)X_ELEMS || s == (long)X_ELEMS * 4) x = (const float*)d_in[i];
        else if (s == (long)W_ELEMS || s == (long)W_ELEMS * 4) w = (const float*)d_in[i];
    }
    float* outf = (float*)d_out;

    long cf = (long)out_size;
    if (cf < 0) cf = 0;
    if (cf > (long)OUT_ELEMS) cf = (long)OUT_ELEMS;
    unsigned capF = (unsigned)cf;

    if (!x || !w) {
        zero_out<<<(capF + 255) / 256, 256>>>(outf, capF);
        return;
    }

    init_tables<<<(KF * FPAD + 255) / 256, 256>>>();

    dim3 gA((MMAX + 63) / 64, NROWS / 64);          // 6 x 1440
    dft_gemm<<<gA, 256>>>(x);

    dim3 gB((LMAX + 63) / 64, NB / 64, MMAX);       // 6 x 4 x 361
    leg_gemm<<<gB, 256>>>(w, outf, capF);
}

// round 12
// speedup vs baseline: 7.9386x; 1.0147x over previous
#include <cuda_runtime.h>

#define NLAT 360
#define NLON 720
#define LMAX 360
#define MMAX 361
#define NB   256                   // B*C
#define NROWS (NB * NLAT)          // 92160
#define KF2  192                   // double-folded K for stage A (12*16), valid n<=180
#define FPAD 384                   // padded MMAX for table rows
#define KBF  192                   // folded K for stage B (12*16), valid k<180

#define X_ELEMS  66355200u         // 256*360*720
#define W_ELEMS  46785600u         // 361*360*360
#define OUT_ELEMS 33269760u        // 256*360*361 floats (real part)

// Double-folded cosine table: g_Ft[n][m] = SC*cos(2*pi*n*m/720)*(0.5 if n in {0,180})
__device__ __align__(256) float g_Ft[KF2 * FPAD];
// Intermediate real spectrum, layout [m][r'], r' = k*NB + bc  (== [m][k][bc])
__device__ __align__(256) float g_X2[(size_t)MMAX * NROWS];

// ---------------------------------------------------------------------------
__global__ void init_tables() {
    unsigned idx = blockIdx.x * blockDim.x + threadIdx.x;
    if (idx >= KF2 * FPAD) return;
    unsigned n = idx / FPAD;
    unsigned m = idx - n * FPAD;
    float v = 0.f;
    if (n <= 180u && m < MMAX) {
        unsigned r = (n * m) % NLON;       // angle = pi * r / 360
        double s, c;
        sincospi((double)r / 360.0, &s, &c);
        double SC = 6.283185307179586476925286766559 / 720.0;
        if (n == 0u || n == 180u) SC *= 0.5;
        v = (float)(SC * c);
    }
    g_Ft[idx] = v;
}

__global__ void zero_out(float* outf, unsigned capF) {
    unsigned i = blockIdx.x * blockDim.x + threadIdx.x;
    if (i < capF) outf[i] = 0.f;
}

// ---------------------------------------------------------------------------
// Stage A v3 (double fold):
//   h_e[n] = (x[n]+x[(720-n)%720]) + (x[360-n]+x[360+n])
//   h_o[n] = (x[n]+x[(720-n)%720]) - (x[360-n]+x[360+n])
//   X2[m][r'] = sum_{n<=180} Ft[n][m] * (m even ? h_e[n] : h_o[n])
// m = m0 + 4*ty + j  => parity(m) = j&1 (m0, 4*ty even): even j <- Ae, odd j <- Ao.
// n in 181..191 (padding): table rows are 0, h garbage is annihilated.
// ---------------------------------------------------------------------------
__global__ __launch_bounds__(256) void dft_gemm(const float* __restrict__ x) {
    __shared__ __align__(16) float Ae[16][64];
    __shared__ __align__(16) float Ao[16][64];
    __shared__ __align__(16) float Bc[16][64];

    unsigned tid = threadIdx.x;
    unsigned tx = tid & 15u, ty = tid >> 4;
    unsigned m0 = blockIdx.x << 6;
    unsigned r0 = blockIdx.y << 6;

    unsigned aI = tid >> 2;            // tile row (0..63)
    unsigned aK = (tid & 3u) << 2;     // n offset (0,4,8,12)
    unsigned bM = tx << 2;

    float acc[4][4];
#pragma unroll
    for (int i = 0; i < 4; i++)
#pragma unroll
        for (int j = 0; j < 4; j++) acc[i][j] = 0.f;

    unsigned rp = r0 + aI;             // r'
    unsigned bc = rp & 255u;
    unsigned k  = rp >> 8;             // fixed per block (64-row tiles, 256 rows/k)
    const float* xRow = x + ((size_t)bc * NLAT + k) * NLON;

    for (unsigned kt = 0; kt < KF2; kt += 16) {
        unsigned n0 = kt + aK;                       // <= 188
        float4 a4 = *(const float4*)(xRow + n0);     // x[n0..n0+3]
        float he[4], ho[4];
        {
            float av[4] = {a4.x, a4.y, a4.z, a4.w};
#pragma unroll
            for (unsigned c = 0; c < 4; c++) {
                unsigned n = n0 + c;                 // <= 191
                float b = __ldg(xRow + ((n == 0u) ? 0u : (NLON - n)));   // x[(720-n)%720]
                float d = __ldg(xRow + (360u - n));  // >= 169, safe
                float e = __ldg(xRow + (360u + n));  // <= 551, safe
                float s1 = av[c] + b;
                float s2 = d + e;
                he[c] = s1 + s2;
                ho[c] = s1 - s2;
            }
        }
        float4 f4 = *(const float4*)(g_Ft + (kt + ty) * FPAD + m0 + bM);
        __syncthreads();
#pragma unroll
        for (unsigned c = 0; c < 4; c++) {
            Ae[aK + c][aI] = he[c];
            Ao[aK + c][aI] = ho[c];
        }
        *(float4*)&Bc[ty][bM] = f4;
        __syncthreads();
#pragma unroll
        for (unsigned kk = 0; kk < 16; kk++) {
            float4 ev = *(const float4*)&Ae[kk][tx << 2];
            float4 ov = *(const float4*)&Ao[kk][tx << 2];
            float4 bv = *(const float4*)&Bc[kk][ty << 2];
            float ee[4] = {ev.x, ev.y, ev.z, ev.w};
            float oo[4] = {ov.x, ov.y, ov.z, ov.w};
#pragma unroll
            for (int i = 0; i < 4; i++) {
                acc[i][0] += ee[i] * bv.x;   // j=0: m even
                acc[i][1] += oo[i] * bv.y;   // j=1: m odd
                acc[i][2] += ee[i] * bv.z;   // j=2: m even
                acc[i][3] += oo[i] * bv.w;   // j=3: m odd
            }
        }
    }

    unsigned rbase = r0 + (tx << 2);
#pragma unroll
    for (unsigned j = 0; j < 4; j++) {
        unsigned m = m0 + (ty << 2) + j;
        if (m < MMAX) {
            float4 v = make_float4(acc[0][j], acc[1][j], acc[2][j], acc[3][j]);
            *(float4*)(g_X2 + (size_t)m * NROWS + rbase) = v;
        }
    }
}

// ---------------------------------------------------------------------------
// Stage B (UNCHANGED, verified R11): GEMM 64(bc) x 64(l) per m, parity-folded K.
// ---------------------------------------------------------------------------
__global__ __launch_bounds__(256) void leg_gemm(const float* __restrict__ w,
                                                float* __restrict__ outf,
                                                unsigned capF) {
    unsigned m   = blockIdx.z;
    unsigned l0  = blockIdx.x << 6;
    unsigned bc0 = blockIdx.y << 6;
    unsigned tid = threadIdx.x;
    unsigned tx = tid & 15u, ty = tid >> 4;

    float acc[4][4];
#pragma unroll
    for (int i = 0; i < 4; i++)
#pragma unroll
        for (int j = 0; j < 4; j++) acc[i][j] = 0.f;

    if (m <= l0 + 63u) {
        __shared__ __align__(16) float Ae[16][64];
        __shared__ __align__(16) float Ao[16][64];
        __shared__ __align__(16) float Bw[16][64];

        unsigned kk = tid >> 4;
        unsigned b4 = (tid & 15u) << 2;
        unsigned lw = tid >> 2;
        unsigned kw = (tid & 3u) << 2;
        bool lvalid = (l0 + lw) < LMAX;

        const float* Xm = g_X2 + (size_t)m * NROWS;
        const float* wL = w + (size_t)m * (LMAX * NLAT) + (size_t)(l0 + lw) * NLAT;

        const float (*Aev)[64];
        const float (*Aod)[64];

        for (unsigned k0 = 0; k0 < KBF; k0 += 16) {
            float4 e4, o4;
            unsigned kg = k0 + kk;
            if (kg < 180u) {
                float4 f = *(const float4*)(Xm + (size_t)kg * NB + bc0 + b4);
                float4 r = *(const float4*)(Xm + (size_t)(359u - kg) * NB + bc0 + b4);
                e4 = make_float4(f.x + r.x, f.y + r.y, f.z + r.z, f.w + r.w);
                o4 = make_float4(f.x - r.x, f.y - r.y, f.z - r.z, f.w - r.w);
            } else {
                e4 = make_float4(0.f, 0.f, 0.f, 0.f);
                o4 = e4;
            }
            float4 w4 = lvalid ? *(const float4*)(wL + k0 + kw)
                               : make_float4(0.f, 0.f, 0.f, 0.f);
            __syncthreads();
            *(float4*)&Ae[kk][b4] = e4;
            *(float4*)&Ao[kk][b4] = o4;
            Bw[kw + 0][lw] = w4.x;
            Bw[kw + 1][lw] = w4.y;
            Bw[kw + 2][lw] = w4.z;
            Bw[kw + 3][lw] = w4.w;
            __syncthreads();

            Aev = (m & 1u) ? Ao : Ae;
            Aod = (m & 1u) ? Ae : Ao;
#pragma unroll
            for (unsigned k = 0; k < 16; k++) {
                float4 ea = *(const float4*)&Aev[k][tx << 2];
                float4 oa = *(const float4*)&Aod[k][tx << 2];
                float4 wv = *(const float4*)&Bw[k][ty << 2];
                float ee[4] = {ea.x, ea.y, ea.z, ea.w};
                float oo[4] = {oa.x, oa.y, oa.z, oa.w};
#pragma unroll
                for (int i = 0; i < 4; i++) {
                    acc[i][0] += ee[i] * wv.x;
                    acc[i][1] += oo[i] * wv.y;
                    acc[i][2] += ee[i] * wv.z;
                    acc[i][3] += oo[i] * wv.w;
                }
            }
        }
    }

#pragma unroll
    for (unsigned i = 0; i < 4; i++) {
        unsigned bc = bc0 + (tx << 2) + i;
#pragma unroll
        for (unsigned j = 0; j < 4; j++) {
            unsigned l = l0 + (ty << 2) + j;
            if (l < LMAX) {
                unsigned oi = (bc * LMAX + l) * MMAX + m;
                if (oi < capF) outf[oi] = acc[i][j];
            }
        }
    }
}

// ---------------------------------------------------------------------------
extern "C" void kernel_launch(void* const* d_in, const int* in_sizes, int n_in,
                              void* d_out, int out_size) {
    const float* x = nullptr;
    const float* w = nullptr;
    for (int i = 0; i < n_in; i++) {
        long s = in_sizes[i];
        if (s == (long)X_ELEMS || s == (long)X_ELEMS * 4) x = (const float*)d_in[i];
        else if (s == (long)W_ELEMS || s == (long)W_ELEMS * 4) w = (const float*)d_in[i];
    }
    float* outf = (float*)d_out;

    long cf = (long)out_size;
    if (cf < 0) cf = 0;
    if (cf > (long)OUT_ELEMS) cf = (long)OUT_ELEMS;
    unsigned capF = (unsigned)cf;

    if (!x || !w) {
        zero_out<<<(capF + 255) / 256, 256>>>(outf, capF);
        return;
    }

    init_tables<<<(KF2 * FPAD + 255) / 256, 256>>>();

    dim3 gA((MMAX + 63) / 64, NROWS / 64);          // 6 x 1440
    dft_gemm<<<gA, 256>>>(x);

    dim3 gB((LMAX + 63) / 64, NB / 64, MMAX);       // 6 x 4 x 361
    leg_gemm<<<gB, 256>>>(w, outf, capF);
}

// round 13
// speedup vs baseline: 9.1355x; 1.1508x over previous
#include <cuda_runtime.h>

#define NLAT 360
#define NLON 720
#define LMAX 360
#define MMAX 361
#define NB   256                   // B*C
#define NROWS (NB * NLAT)          // 92160
#define KF2  192                   // double-folded K for stage A (12*16), valid n<=180
#define FPAD 384                   // padded MMAX for table rows
#define KBF  192                   // folded K for stage B (12*16), valid k<180

#define X_ELEMS  66355200u         // 256*360*720
#define W_ELEMS  46785600u         // 361*360*360
#define OUT_ELEMS 33269760u        // 256*360*361 floats (real part)

// Double-folded cosine table: g_Ft[n][m] = SC*cos(2*pi*n*m/720)*(0.5 if n in {0,180})
__device__ __align__(256) float g_Ft[KF2 * FPAD];
// Pre-folded input: g_He/g_Ho [r'][n], r' = k*NB + bc, n < KF2 (zeros for n>180)
__device__ __align__(256) float g_He[(size_t)NROWS * KF2];
__device__ __align__(256) float g_Ho[(size_t)NROWS * KF2];
// Intermediate real spectrum, layout [m][r'], r' = k*NB + bc  (== [m][k][bc])
__device__ __align__(256) float g_X2[(size_t)MMAX * NROWS];

// ---------------------------------------------------------------------------
__global__ void init_tables() {
    unsigned idx = blockIdx.x * blockDim.x + threadIdx.x;
    if (idx >= KF2 * FPAD) return;
    unsigned n = idx / FPAD;
    unsigned m = idx - n * FPAD;
    float v = 0.f;
    if (n <= 180u && m < MMAX) {
        unsigned r = (n * m) % NLON;       // angle = pi * r / 360
        double s, c;
        sincospi((double)r / 360.0, &s, &c);
        double SC = 6.283185307179586476925286766559 / 720.0;
        if (n == 0u || n == 180u) SC *= 0.5;
        v = (float)(SC * c);
    }
    g_Ft[idx] = v;
}

__global__ void zero_out(float* outf, unsigned capF) {
    unsigned i = blockIdx.x * blockDim.x + threadIdx.x;
    if (i < capF) outf[i] = 0.f;
}

// ---------------------------------------------------------------------------
// Fold pass: one block per input row (bc,k).
//   s1 = x[n] + x[(720-n)%720],  s2 = x[360-n] + x[360+n]
//   He[r'][n] = s1 + s2,  Ho[r'][n] = s1 - s2   (n <= 180; zeros above)
// ---------------------------------------------------------------------------
__global__ __launch_bounds__(256) void fold_x(const float* __restrict__ x) {
    __shared__ float xs[NLON];
    unsigned rp = blockIdx.x;            // r' = k*256 + bc
    unsigned bc = rp & 255u;
    unsigned k  = rp >> 8;
    unsigned t  = threadIdx.x;

    const float* xRow = x + ((size_t)bc * NLAT + k) * NLON;
    if (t < 180u)
        *(float4*)&xs[t << 2] = *(const float4*)(xRow + (t << 2));
    __syncthreads();

    float* he = g_He + (size_t)rp * KF2;
    float* ho = g_Ho + (size_t)rp * KF2;
    if (t < KF2) {
        float ve = 0.f, vo = 0.f;
        if (t <= 180u) {
            float a = xs[t];
            float b = xs[(t == 0u) ? 0u : (NLON - t)];
            float d = xs[360u - t];
            float e = xs[(360u + t) % NLON];   // t=0 -> 360; t<=180 -> <=540
            float s1 = a + b;
            float s2 = d + e;
            ve = s1 + s2;
            vo = s1 - s2;
        }
        he[t] = ve;
        ho[t] = vo;
    }
}

// ---------------------------------------------------------------------------
// Stage A v4: X2[m][r'] = sum_{n<=180} Ft[n][m] * (m even ? He : Ho)[r'][n]
// 64(r') x 64(m) tile, K=192 in 12 steps of 16. Software-pipelined LDGs.
// m = m0 + 4*ty + j => parity = j&1: even j <- Ae, odd j <- Ao.
// ---------------------------------------------------------------------------
__global__ __launch_bounds__(256) void dft_gemm() {
    __shared__ __align__(16) float Ae[16][64];
    __shared__ __align__(16) float Ao[16][64];
    __shared__ __align__(16) float Bc[16][64];

    unsigned tid = threadIdx.x;
    unsigned tx = tid & 15u, ty = tid >> 4;
    unsigned m0 = blockIdx.x << 6;
    unsigned r0 = blockIdx.y << 6;

    unsigned aI = tid >> 2;            // tile row (0..63)
    unsigned aK = (tid & 3u) << 2;     // n offset (0,4,8,12)
    unsigned bM = tx << 2;

    float acc[4][4];
#pragma unroll
    for (int i = 0; i < 4; i++)
#pragma unroll
        for (int j = 0; j < 4; j++) acc[i][j] = 0.f;

    unsigned rp = r0 + aI;
    const float* heRow = g_He + (size_t)rp * KF2;
    const float* hoRow = g_Ho + (size_t)rp * KF2;
    const float* ftCol = g_Ft + m0 + bM;

    // preload tile 0
    float4 he4 = *(const float4*)(heRow + aK);
    float4 ho4 = *(const float4*)(hoRow + aK);
    float4 f4  = *(const float4*)(ftCol + ty * FPAD);

    for (unsigned kt = 0; kt < KF2; kt += 16) {
        __syncthreads();
        Ae[aK + 0][aI] = he4.x; Ae[aK + 1][aI] = he4.y;
        Ae[aK + 2][aI] = he4.z; Ae[aK + 3][aI] = he4.w;
        Ao[aK + 0][aI] = ho4.x; Ao[aK + 1][aI] = ho4.y;
        Ao[aK + 2][aI] = ho4.z; Ao[aK + 3][aI] = ho4.w;
        *(float4*)&Bc[ty][bM] = f4;
        __syncthreads();

        if (kt + 16 < KF2) {           // prefetch next tile (hidden by compute)
            he4 = *(const float4*)(heRow + kt + 16 + aK);
            ho4 = *(const float4*)(hoRow + kt + 16 + aK);
            f4  = *(const float4*)(ftCol + (kt + 16 + ty) * FPAD);
        }

#pragma unroll
        for (unsigned kk = 0; kk < 16; kk++) {
            float4 ev = *(const float4*)&Ae[kk][tx << 2];
            float4 ov = *(const float4*)&Ao[kk][tx << 2];
            float4 bv = *(const float4*)&Bc[kk][ty << 2];
            float ee[4] = {ev.x, ev.y, ev.z, ev.w};
            float oo[4] = {ov.x, ov.y, ov.z, ov.w};
#pragma unroll
            for (int i = 0; i < 4; i++) {
                acc[i][0] += ee[i] * bv.x;   // j=0: m even
                acc[i][1] += oo[i] * bv.y;   // j=1: m odd
                acc[i][2] += ee[i] * bv.z;   // j=2: m even
                acc[i][3] += oo[i] * bv.w;   // j=3: m odd
            }
        }
    }

    unsigned rbase = r0 + (tx << 2);
#pragma unroll
    for (unsigned j = 0; j < 4; j++) {
        unsigned m = m0 + (ty << 2) + j;
        if (m < MMAX) {
            float4 v = make_float4(acc[0][j], acc[1][j], acc[2][j], acc[3][j]);
            *(float4*)(g_X2 + (size_t)m * NROWS + rbase) = v;
        }
    }
}

// ---------------------------------------------------------------------------
// Stage B (R11 logic + software pipelining): GEMM 64(bc) x 64(l) per m.
//   out[bc,l,m] = sum_{k<180} w[m,l,k] * (X[k] +/- X[359-k]) by (l+m) parity.
// ---------------------------------------------------------------------------
__global__ __launch_bounds__(256) void leg_gemm(const float* __restrict__ w,
                                                float* __restrict__ outf,
                                                unsigned capF) {
    unsigned m   = blockIdx.z;
    unsigned l0  = blockIdx.x << 6;
    unsigned bc0 = blockIdx.y << 6;
    unsigned tid = threadIdx.x;
    unsigned tx = tid & 15u, ty = tid >> 4;

    float acc[4][4];
#pragma unroll
    for (int i = 0; i < 4; i++)
#pragma unroll
        for (int j = 0; j < 4; j++) acc[i][j] = 0.f;

    if (m <= l0 + 63u) {
        __shared__ __align__(16) float Ae[16][64];
        __shared__ __align__(16) float Ao[16][64];
        __shared__ __align__(16) float Bw[16][64];

        unsigned kk = tid >> 4;            // k row for A loads (0..15)
        unsigned b4 = (tid & 15u) << 2;    // bc offset (float4)
        unsigned lw = tid >> 2;            // l for w loads (0..63)
        unsigned kw = (tid & 3u) << 2;     // k offset for w loads
        bool lvalid = (l0 + lw) < LMAX;

        const float* Xm = g_X2 + (size_t)m * NROWS;
        const float* wL = w + (size_t)m * (LMAX * NLAT) + (size_t)(l0 + lw) * NLAT;

        const float (*Aev)[64] = (m & 1u) ? Ao : Ae;   // source for even j
        const float (*Aod)[64] = (m & 1u) ? Ae : Ao;   // source for odd j

        // preload tile 0
        float4 fv = make_float4(0.f, 0.f, 0.f, 0.f), rv = fv, w4 = fv;
        if (kk < 180u) {
            fv = *(const float4*)(Xm + (size_t)kk * NB + bc0 + b4);
            rv = *(const float4*)(Xm + (size_t)(359u - kk) * NB + bc0 + b4);
        }
        if (lvalid) w4 = *(const float4*)(wL + kw);

        for (unsigned k0 = 0; k0 < KBF; k0 += 16) {
            __syncthreads();
            Ae[kk][b4 + 0] = fv.x + rv.x; Ae[kk][b4 + 1] = fv.y + rv.y;
            Ae[kk][b4 + 2] = fv.z + rv.z; Ae[kk][b4 + 3] = fv.w + rv.w;
            Ao[kk][b4 + 0] = fv.x - rv.x; Ao[kk][b4 + 1] = fv.y - rv.y;
            Ao[kk][b4 + 2] = fv.z - rv.z; Ao[kk][b4 + 3] = fv.w - rv.w;
            Bw[kw + 0][lw] = w4.x;
            Bw[kw + 1][lw] = w4.y;
            Bw[kw + 2][lw] = w4.z;
            Bw[kw + 3][lw] = w4.w;
            __syncthreads();

            if (k0 + 16 < KBF) {           // prefetch next tile
                unsigned kg = k0 + 16 + kk;
                fv = make_float4(0.f, 0.f, 0.f, 0.f); rv = fv; w4 = fv;
                if (kg < 180u) {
                    fv = *(const float4*)(Xm + (size_t)kg * NB + bc0 + b4);
                    rv = *(const float4*)(Xm + (size_t)(359u - kg) * NB + bc0 + b4);
                }
                if (lvalid) w4 = *(const float4*)(wL + k0 + 16 + kw);
            }

#pragma unroll
            for (unsigned k = 0; k < 16; k++) {
                float4 ea = *(const float4*)&Aev[k][tx << 2];
                float4 oa = *(const float4*)&Aod[k][tx << 2];
                float4 wv = *(const float4*)&Bw[k][ty << 2];
                float ee[4] = {ea.x, ea.y, ea.z, ea.w};
                float oo[4] = {oa.x, oa.y, oa.z, oa.w};
#pragma unroll
                for (int i = 0; i < 4; i++) {
                    acc[i][0] += ee[i] * wv.x;
                    acc[i][1] += oo[i] * wv.y;
                    acc[i][2] += ee[i] * wv.z;
                    acc[i][3] += oo[i] * wv.w;
                }
            }
        }
    }

#pragma unroll
    for (unsigned i = 0; i < 4; i++) {
        unsigned bc = bc0 + (tx << 2) + i;
#pragma unroll
        for (unsigned j = 0; j < 4; j++) {
            unsigned l = l0 + (ty << 2) + j;
            if (l < LMAX) {
                unsigned oi = (bc * LMAX + l) * MMAX + m;
                if (oi < capF) outf[oi] = acc[i][j];
            }
        }
    }
}

// ---------------------------------------------------------------------------
extern "C" void kernel_launch(void* const* d_in, const int* in_sizes, int n_in,
                              void* d_out, int out_size) {
    const float* x = nullptr;
    const float* w = nullptr;
    for (int i = 0; i < n_in; i++) {
        long s = in_sizes[i];
        if (s == (long)X_ELEMS || s == (long)X_ELEMS * 4) x = (const float*)d_in[i];
        else if (s == (long)W_ELEMS || s == (long)W_ELEMS * 4) w = (const float*)d_in[i];
    }
    float* outf = (float*)d_out;

    long cf = (long)out_size;
    if (cf < 0) cf = 0;
    if (cf > (long)OUT_ELEMS) cf = (long)OUT_ELEMS;
    unsigned capF = (unsigned)cf;

    if (!x || !w) {
        zero_out<<<(capF + 255) / 256, 256>>>(outf, capF);
        return;
    }

    init_tables<<<(KF2 * FPAD + 255) / 256, 256>>>();

    fold_x<<<NROWS, 256>>>(x);                      // 92160 blocks

    dim3 gA((MMAX + 63) / 64, NROWS / 64);          // 6 x 1440
    dft_gemm<<<gA, 256>>>();

    dim3 gB((LMAX + 63) / 64, NB / 64, MMAX);       // 6 x 4 x 361
    leg_gemm<<<gB, 256>>>(w, outf, capF);
}

// round 14
// speedup vs baseline: 11.9335x; 1.3063x over previous
#include <cuda_runtime.h>

#define NLAT 360
#define NLON 720
#define LMAX 360
#define MMAX 361
#define NB   256                   // B*C
#define NROWS (NB * NLAT)          // 92160
#define KF2  192                   // double-folded K for stage A (12*16), valid n<=180
#define FPAD 384                   // padded MMAX for table rows
#define KBF  192                   // folded K for stage B (12*16), valid k<180

#define X_ELEMS  66355200u
#define W_ELEMS  46785600u
#define OUT_ELEMS 33269760u

__device__ __align__(256) float g_Ft[KF2 * FPAD];
__device__ __align__(256) float g_He[(size_t)NROWS * KF2];
__device__ __align__(256) float g_Ho[(size_t)NROWS * KF2];
__device__ __align__(256) float g_X2[(size_t)MMAX * NROWS];

// ---------------------------------------------------------------------------
__global__ void init_tables() {
    unsigned idx = blockIdx.x * blockDim.x + threadIdx.x;
    if (idx >= KF2 * FPAD) return;
    unsigned n = idx / FPAD;
    unsigned m = idx - n * FPAD;
    float v = 0.f;
    if (n <= 180u && m < MMAX) {
        unsigned r = (n * m) % NLON;
        double s, c;
        sincospi((double)r / 360.0, &s, &c);
        double SC = 6.283185307179586476925286766559 / 720.0;
        if (n == 0u || n == 180u) SC *= 0.5;
        v = (float)(SC * c);
    }
    g_Ft[idx] = v;
}

__global__ void zero_out(float* outf, unsigned capF) {
    unsigned i = blockIdx.x * blockDim.x + threadIdx.x;
    if (i < capF) outf[i] = 0.f;
}

// ---------------------------------------------------------------------------
// Fold pass (verified R13): He/Ho[r'][n]
// ---------------------------------------------------------------------------
__global__ __launch_bounds__(256) void fold_x(const float* __restrict__ x) {
    __shared__ float xs[NLON];
    unsigned rp = blockIdx.x;            // r' = k*256 + bc
    unsigned bc = rp & 255u;
    unsigned k  = rp >> 8;
    unsigned t  = threadIdx.x;

    const float* xRow = x + ((size_t)bc * NLAT + k) * NLON;
    if (t < 180u)
        *(float4*)&xs[t << 2] = *(const float4*)(xRow + (t << 2));
    __syncthreads();

    float* he = g_He + (size_t)rp * KF2;
    float* ho = g_Ho + (size_t)rp * KF2;
    if (t < KF2) {
        float ve = 0.f, vo = 0.f;
        if (t <= 180u) {
            float a = xs[t];
            float b = xs[(t == 0u) ? 0u : (NLON - t)];
            float d = xs[360u - t];
            float e = xs[(360u + t) % NLON];
            float s1 = a + b;
            float s2 = d + e;
            ve = s1 + s2;
            vo = s1 - s2;
        }
        he[t] = ve;
        ho[t] = vo;
    }
}

// ---------------------------------------------------------------------------
// Stage A v5: 128(r') x 128(m) tile, 8x8 frags, K=192 pipelined.
// X2[m][r'] = sum_n Ft[n][m] * (m even ? He : Ho)[r'][n];  col parity = j&1.
// ---------------------------------------------------------------------------
__global__ __launch_bounds__(256) void dft_gemm() {
    __shared__ __align__(16) float Ae[16][128];
    __shared__ __align__(16) float Ao[16][128];
    __shared__ __align__(16) float Bc[16][128];

    unsigned tid = threadIdx.x;
    unsigned tx = tid & 15u, ty = tid >> 4;
    unsigned m0 = blockIdx.x << 7;       // 0,128,256
    unsigned r0 = blockIdx.y << 7;       // 720 tiles

    unsigned aR = tid >> 1;              // 0..127 (He/Ho row)
    unsigned aN = (tid & 1u) << 3;       // 0 or 8
    unsigned bN = tid >> 4;              // 0..15 (table n-row)
    unsigned bM = (tid & 15u) << 2;      // 0..60

    float acc[8][8];
#pragma unroll
    for (int i = 0; i < 8; i++)
#pragma unroll
        for (int j = 0; j < 8; j++) acc[i][j] = 0.f;

    const float* heRow = g_He + (size_t)(r0 + aR) * KF2;
    const float* hoRow = g_Ho + (size_t)(r0 + aR) * KF2;
    const float* ftB   = g_Ft + m0 + bM;

    float4 hea = *(const float4*)(heRow + aN);
    float4 heb = *(const float4*)(heRow + aN + 4);
    float4 hoa = *(const float4*)(hoRow + aN);
    float4 hob = *(const float4*)(hoRow + aN + 4);
    float4 fa  = *(const float4*)(ftB + bN * FPAD);
    float4 fb  = *(const float4*)(ftB + bN * FPAD + 64);

    for (unsigned kt = 0; kt < KF2; kt += 16) {
        __syncthreads();
        Ae[aN + 0][aR] = hea.x; Ae[aN + 1][aR] = hea.y;
        Ae[aN + 2][aR] = hea.z; Ae[aN + 3][aR] = hea.w;
        Ae[aN + 4][aR] = heb.x; Ae[aN + 5][aR] = heb.y;
        Ae[aN + 6][aR] = heb.z; Ae[aN + 7][aR] = heb.w;
        Ao[aN + 0][aR] = hoa.x; Ao[aN + 1][aR] = hoa.y;
        Ao[aN + 2][aR] = hoa.z; Ao[aN + 3][aR] = hoa.w;
        Ao[aN + 4][aR] = hob.x; Ao[aN + 5][aR] = hob.y;
        Ao[aN + 6][aR] = hob.z; Ao[aN + 7][aR] = hob.w;
        *(float4*)&Bc[bN][bM]      = fa;
        *(float4*)&Bc[bN][bM + 64] = fb;
        __syncthreads();

        if (kt + 16 < KF2) {
            hea = *(const float4*)(heRow + kt + 16 + aN);
            heb = *(const float4*)(heRow + kt + 16 + aN + 4);
            hoa = *(const float4*)(hoRow + kt + 16 + aN);
            hob = *(const float4*)(hoRow + kt + 16 + aN + 4);
            fa  = *(const float4*)(ftB + (kt + 16 + bN) * FPAD);
            fb  = *(const float4*)(ftB + (kt + 16 + bN) * FPAD + 64);
        }

#pragma unroll
        for (unsigned k = 0; k < 16; k++) {
            float4 e0 = *(const float4*)&Ae[k][tx << 2];
            float4 e1 = *(const float4*)&Ae[k][64 + (tx << 2)];
            float4 o0 = *(const float4*)&Ao[k][tx << 2];
            float4 o1 = *(const float4*)&Ao[k][64 + (tx << 2)];
            float4 c0 = *(const float4*)&Bc[k][ty << 2];
            float4 c1 = *(const float4*)&Bc[k][64 + (ty << 2)];
            float ee[8] = {e0.x, e0.y, e0.z, e0.w, e1.x, e1.y, e1.z, e1.w};
            float oo[8] = {o0.x, o0.y, o0.z, o0.w, o1.x, o1.y, o1.z, o1.w};
#pragma unroll
            for (int i = 0; i < 8; i++) {
                acc[i][0] += ee[i] * c0.x;
                acc[i][1] += oo[i] * c0.y;
                acc[i][2] += ee[i] * c0.z;
                acc[i][3] += oo[i] * c0.w;
                acc[i][4] += ee[i] * c1.x;
                acc[i][5] += oo[i] * c1.y;
                acc[i][6] += ee[i] * c1.z;
                acc[i][7] += oo[i] * c1.w;
            }
        }
    }

#pragma unroll
    for (unsigned jh = 0; jh < 2; jh++)
#pragma unroll
        for (unsigned j = 0; j < 4; j++) {
            unsigned m = m0 + jh * 64u + (ty << 2) + j;
            if (m < MMAX) {
                unsigned jc = jh * 4u + j;
                float4 v0 = make_float4(acc[0][jc], acc[1][jc], acc[2][jc], acc[3][jc]);
                float4 v1 = make_float4(acc[4][jc], acc[5][jc], acc[6][jc], acc[7][jc]);
                float* dst = g_X2 + (size_t)m * NROWS + r0;
                *(float4*)(dst + (tx << 2))       = v0;
                *(float4*)(dst + 64 + (tx << 2))  = v1;
            }
        }
}

// ---------------------------------------------------------------------------
// Stage B v3: 128(bc) x 128(l) tile per m, 8x8 frags, parity-folded K=192.
// ---------------------------------------------------------------------------
__global__ __launch_bounds__(256) void leg_gemm(const float* __restrict__ w,
                                                float* __restrict__ outf,
                                                unsigned capF) {
    unsigned m   = blockIdx.z;
    unsigned l0  = blockIdx.x << 7;      // 0,128,256
    unsigned bc0 = blockIdx.y << 7;      // 0,128
    unsigned tid = threadIdx.x;
    unsigned tx = tid & 15u, ty = tid >> 4;

    float acc[8][8];
#pragma unroll
    for (int i = 0; i < 8; i++)
#pragma unroll
        for (int j = 0; j < 8; j++) acc[i][j] = 0.f;

    if (m <= l0 + 127u) {
        __shared__ __align__(16) float Ae[16][128];
        __shared__ __align__(16) float Ao[16][128];
        __shared__ __align__(16) float Bw[16][128];

        unsigned kk = tid >> 4;              // 0..15 (k row for X loads)
        unsigned b4 = (tid & 15u) << 2;      // 0..60 (bc offset)
        unsigned lw = tid >> 1;              // 0..127 (l for w loads)
        unsigned kw = (tid & 1u) << 3;       // 0 or 8
        bool lvalid = (l0 + lw) < LMAX;

        const float* Xm = g_X2 + (size_t)m * NROWS;
        const float* wL = w + (size_t)m * (LMAX * NLAT) + (size_t)(l0 + lw) * NLAT;

        const float (*Aev)[128] = (m & 1u) ? Ao : Ae;   // source for even j
        const float (*Aod)[128] = (m & 1u) ? Ae : Ao;   // source for odd j

        float4 z4 = make_float4(0.f, 0.f, 0.f, 0.f);
        float4 fv0 = z4, fv1 = z4, rv0 = z4, rv1 = z4, wa = z4, wb = z4;
        if (kk < 180u) {
            const float* pf = Xm + (size_t)kk * NB + bc0 + b4;
            const float* pr = Xm + (size_t)(359u - kk) * NB + bc0 + b4;
            fv0 = *(const float4*)pf;       fv1 = *(const float4*)(pf + 64);
            rv0 = *(const float4*)pr;       rv1 = *(const float4*)(pr + 64);
        }
        if (lvalid) {
            wa = *(const float4*)(wL + kw);
            wb = *(const float4*)(wL + kw + 4);
        }

        for (unsigned k0 = 0; k0 < KBF; k0 += 16) {
            __syncthreads();
            {
                float4 e0 = make_float4(fv0.x + rv0.x, fv0.y + rv0.y, fv0.z + rv0.z, fv0.w + rv0.w);
                float4 e1 = make_float4(fv1.x + rv1.x, fv1.y + rv1.y, fv1.z + rv1.z, fv1.w + rv1.w);
                float4 o0 = make_float4(fv0.x - rv0.x, fv0.y - rv0.y, fv0.z - rv0.z, fv0.w - rv0.w);
                float4 o1 = make_float4(fv1.x - rv1.x, fv1.y - rv1.y, fv1.z - rv1.z, fv1.w - rv1.w);
                *(float4*)&Ae[kk][b4]      = e0;
                *(float4*)&Ae[kk][b4 + 64] = e1;
                *(float4*)&Ao[kk][b4]      = o0;
                *(float4*)&Ao[kk][b4 + 64] = o1;
            }
            Bw[kw + 0][lw] = wa.x; Bw[kw + 1][lw] = wa.y;
            Bw[kw + 2][lw] = wa.z; Bw[kw + 3][lw] = wa.w;
            Bw[kw + 4][lw] = wb.x; Bw[kw + 5][lw] = wb.y;
            Bw[kw + 6][lw] = wb.z; Bw[kw + 7][lw] = wb.w;
            __syncthreads();

            if (k0 + 16 < KBF) {
                unsigned kg = k0 + 16 + kk;
                fv0 = z4; fv1 = z4; rv0 = z4; rv1 = z4; wa = z4; wb = z4;
                if (kg < 180u) {
                    const float* pf = Xm + (size_t)kg * NB + bc0 + b4;
                    const float* pr = Xm + (size_t)(359u - kg) * NB + bc0 + b4;
                    fv0 = *(const float4*)pf;   fv1 = *(const float4*)(pf + 64);
                    rv0 = *(const float4*)pr;   rv1 = *(const float4*)(pr + 64);
                }
                if (lvalid) {
                    wa = *(const float4*)(wL + k0 + 16 + kw);
                    wb = *(const float4*)(wL + k0 + 16 + kw + 4);
                }
            }

#pragma unroll
            for (unsigned k = 0; k < 16; k++) {
                float4 e0 = *(const float4*)&Aev[k][tx << 2];
                float4 e1 = *(const float4*)&Aev[k][64 + (tx << 2)];
                float4 o0 = *(const float4*)&Aod[k][tx << 2];
                float4 o1 = *(const float4*)&Aod[k][64 + (tx << 2)];
                float4 c0 = *(const float4*)&Bw[k][ty << 2];
                float4 c1 = *(const float4*)&Bw[k][64 + (ty << 2)];
                float ee[8] = {e0.x, e0.y, e0.z, e0.w, e1.x, e1.y, e1.z, e1.w};
                float oo[8] = {o0.x, o0.y, o0.z, o0.w, o1.x, o1.y, o1.z, o1.w};
#pragma unroll
                for (int i = 0; i < 8; i++) {
                    acc[i][0] += ee[i] * c0.x;
                    acc[i][1] += oo[i] * c0.y;
                    acc[i][2] += ee[i] * c0.z;
                    acc[i][3] += oo[i] * c0.w;
                    acc[i][4] += ee[i] * c1.x;
                    acc[i][5] += oo[i] * c1.y;
                    acc[i][6] += ee[i] * c1.z;
                    acc[i][7] += oo[i] * c1.w;
                }
            }
        }
    }

#pragma unroll
    for (unsigned ih = 0; ih < 2; ih++)
#pragma unroll
        for (unsigned i = 0; i < 4; i++) {
            unsigned bc = bc0 + ih * 64u + (tx << 2) + i;
#pragma unroll
            for (unsigned jh = 0; jh < 2; jh++)
#pragma unroll
                for (unsigned j = 0; j < 4; j++) {
                    unsigned l = l0 + jh * 64u + (ty << 2) + j;
                    if (l < LMAX) {
                        unsigned oi = (bc * LMAX + l) * MMAX + m;
                        if (oi < capF) outf[oi] = acc[ih * 4 + i][jh * 4 + j];
                    }
                }
        }
}

// ---------------------------------------------------------------------------
extern "C" void kernel_launch(void* const* d_in, const int* in_sizes, int n_in,
                              void* d_out, int out_size) {
    const float* x = nullptr;
    const float* w = nullptr;
    for (int i = 0; i < n_in; i++) {
        long s = in_sizes[i];
        if (s == (long)X_ELEMS || s == (long)X_ELEMS * 4) x = (const float*)d_in[i];
        else if (s == (long)W_ELEMS || s == (long)W_ELEMS * 4) w = (const float*)d_in[i];
    }
    float* outf = (float*)d_out;

    long cf = (long)out_size;
    if (cf < 0) cf = 0;
    if (cf > (long)OUT_ELEMS) cf = (long)OUT_ELEMS;
    unsigned capF = (unsigned)cf;

    if (!x || !w) {
        zero_out<<<(capF + 255) / 256, 256>>>(outf, capF);
        return;
    }

    init_tables<<<(KF2 * FPAD + 255) / 256, 256>>>();

    fold_x<<<NROWS, 256>>>(x);                      // 92160 blocks

    dim3 gA(3, NROWS / 128);                        // 3 x 720
    dft_gemm<<<gA, 256>>>();

    dim3 gB(3, NB / 128, MMAX);                     // 3 x 2 x 361
    leg_gemm<<<gB, 256>>>(w, outf, capF);
}

// round 15
// speedup vs baseline: 12.2468x; 1.0262x over previous
#include <cuda_runtime.h>

#define NLAT 360
#define NLON 720
#define LMAX 360
#define MMAX 361
#define NB   256                   // B*C
#define NROWS (NB * NLAT)          // 92160
#define KF2  192                   // double-folded K for stage A (12*16), valid n<=180
#define FPAD 384                   // padded MMAX for table rows
#define KBF  192                   // folded K for stage B (12*16), valid k<180

#define X_ELEMS  66355200u
#define W_ELEMS  46785600u
#define OUT_ELEMS 33269760u

__device__ __align__(256) float g_Ft[KF2 * FPAD];
__device__ __align__(256) float g_He[(size_t)NROWS * KF2];
__device__ __align__(256) float g_Ho[(size_t)NROWS * KF2];
__device__ __align__(256) float g_X2[(size_t)MMAX * NROWS];

// ---------------------------------------------------------------------------
__global__ void init_tables() {
    unsigned idx = blockIdx.x * blockDim.x + threadIdx.x;
    if (idx >= KF2 * FPAD) return;
    unsigned n = idx / FPAD;
    unsigned m = idx - n * FPAD;
    float v = 0.f;
    if (n <= 180u && m < MMAX) {
        unsigned r = (n * m) % NLON;
        double s, c;
        sincospi((double)r / 360.0, &s, &c);
        double SC = 6.283185307179586476925286766559 / 720.0;
        if (n == 0u || n == 180u) SC *= 0.5;
        v = (float)(SC * c);
    }
    g_Ft[idx] = v;
}

__global__ void zero_out(float* outf, unsigned capF) {
    unsigned i = blockIdx.x * blockDim.x + threadIdx.x;
    if (i < capF) outf[i] = 0.f;
}

// ---------------------------------------------------------------------------
// Fold pass (verified R13): He/Ho[r'][n]
// ---------------------------------------------------------------------------
__global__ __launch_bounds__(256) void fold_x(const float* __restrict__ x) {
    __shared__ float xs[NLON];
    unsigned rp = blockIdx.x;            // r' = k*256 + bc
    unsigned bc = rp & 255u;
    unsigned k  = rp >> 8;
    unsigned t  = threadIdx.x;

    const float* xRow = x + ((size_t)bc * NLAT + k) * NLON;
    if (t < 180u)
        *(float4*)&xs[t << 2] = *(const float4*)(xRow + (t << 2));
    __syncthreads();

    float* he = g_He + (size_t)rp * KF2;
    float* ho = g_Ho + (size_t)rp * KF2;
    if (t < KF2) {
        float ve = 0.f, vo = 0.f;
        if (t <= 180u) {
            float a = xs[t];
            float b = xs[(t == 0u) ? 0u : (NLON - t)];
            float d = xs[360u - t];
            float e = xs[(360u + t) % NLON];
            float s1 = a + b;
            float s2 = d + e;
            ve = s1 + s2;
            vo = s1 - s2;
        }
        he[t] = ve;
        ho[t] = vo;
    }
}

// ---------------------------------------------------------------------------
// Stage A (UNCHANGED, verified R14 — at FFMA floor): 128x128 tile, 8x8 frags.
// ---------------------------------------------------------------------------
__global__ __launch_bounds__(256) void dft_gemm() {
    __shared__ __align__(16) float Ae[16][128];
    __shared__ __align__(16) float Ao[16][128];
    __shared__ __align__(16) float Bc[16][128];

    unsigned tid = threadIdx.x;
    unsigned tx = tid & 15u, ty = tid >> 4;
    unsigned m0 = blockIdx.x << 7;
    unsigned r0 = blockIdx.y << 7;

    unsigned aR = tid >> 1;
    unsigned aN = (tid & 1u) << 3;
    unsigned bN = tid >> 4;
    unsigned bM = (tid & 15u) << 2;

    float acc[8][8];
#pragma unroll
    for (int i = 0; i < 8; i++)
#pragma unroll
        for (int j = 0; j < 8; j++) acc[i][j] = 0.f;

    const float* heRow = g_He + (size_t)(r0 + aR) * KF2;
    const float* hoRow = g_Ho + (size_t)(r0 + aR) * KF2;
    const float* ftB   = g_Ft + m0 + bM;

    float4 hea = *(const float4*)(heRow + aN);
    float4 heb = *(const float4*)(heRow + aN + 4);
    float4 hoa = *(const float4*)(hoRow + aN);
    float4 hob = *(const float4*)(hoRow + aN + 4);
    float4 fa  = *(const float4*)(ftB + bN * FPAD);
    float4 fb  = *(const float4*)(ftB + bN * FPAD + 64);

    for (unsigned kt = 0; kt < KF2; kt += 16) {
        __syncthreads();
        Ae[aN + 0][aR] = hea.x; Ae[aN + 1][aR] = hea.y;
        Ae[aN + 2][aR] = hea.z; Ae[aN + 3][aR] = hea.w;
        Ae[aN + 4][aR] = heb.x; Ae[aN + 5][aR] = heb.y;
        Ae[aN + 6][aR] = heb.z; Ae[aN + 7][aR] = heb.w;
        Ao[aN + 0][aR] = hoa.x; Ao[aN + 1][aR] = hoa.y;
        Ao[aN + 2][aR] = hoa.z; Ao[aN + 3][aR] = hoa.w;
        Ao[aN + 4][aR] = hob.x; Ao[aN + 5][aR] = hob.y;
        Ao[aN + 6][aR] = hob.z; Ao[aN + 7][aR] = hob.w;
        *(float4*)&Bc[bN][bM]      = fa;
        *(float4*)&Bc[bN][bM + 64] = fb;
        __syncthreads();

        if (kt + 16 < KF2) {
            hea = *(const float4*)(heRow + kt + 16 + aN);
            heb = *(const float4*)(heRow + kt + 16 + aN + 4);
            hoa = *(const float4*)(hoRow + kt + 16 + aN);
            hob = *(const float4*)(hoRow + kt + 16 + aN + 4);
            fa  = *(const float4*)(ftB + (kt + 16 + bN) * FPAD);
            fb  = *(const float4*)(ftB + (kt + 16 + bN) * FPAD + 64);
        }

#pragma unroll
        for (unsigned k = 0; k < 16; k++) {
            float4 e0 = *(const float4*)&Ae[k][tx << 2];
            float4 e1 = *(const float4*)&Ae[k][64 + (tx << 2)];
            float4 o0 = *(const float4*)&Ao[k][tx << 2];
            float4 o1 = *(const float4*)&Ao[k][64 + (tx << 2)];
            float4 c0 = *(const float4*)&Bc[k][ty << 2];
            float4 c1 = *(const float4*)&Bc[k][64 + (ty << 2)];
            float ee[8] = {e0.x, e0.y, e0.z, e0.w, e1.x, e1.y, e1.z, e1.w};
            float oo[8] = {o0.x, o0.y, o0.z, o0.w, o1.x, o1.y, o1.z, o1.w};
#pragma unroll
            for (int i = 0; i < 8; i++) {
                acc[i][0] += ee[i] * c0.x;
                acc[i][1] += oo[i] * c0.y;
                acc[i][2] += ee[i] * c0.z;
                acc[i][3] += oo[i] * c0.w;
                acc[i][4] += ee[i] * c1.x;
                acc[i][5] += oo[i] * c1.y;
                acc[i][6] += ee[i] * c1.z;
                acc[i][7] += oo[i] * c1.w;
            }
        }
    }

#pragma unroll
    for (unsigned jh = 0; jh < 2; jh++)
#pragma unroll
        for (unsigned j = 0; j < 4; j++) {
            unsigned m = m0 + jh * 64u + (ty << 2) + j;
            if (m < MMAX) {
                unsigned jc = jh * 4u + j;
                float4 v0 = make_float4(acc[0][jc], acc[1][jc], acc[2][jc], acc[3][jc]);
                float4 v1 = make_float4(acc[4][jc], acc[5][jc], acc[6][jc], acc[7][jc]);
                float* dst = g_X2 + (size_t)m * NROWS + r0;
                *(float4*)(dst + (tx << 2))       = v0;
                *(float4*)(dst + 64 + (tx << 2))  = v1;
            }
        }
}

// ---------------------------------------------------------------------------
// Stage B v4: identical math to verified R14, but __launch_bounds__(256, 2)
// -> <=128 regs -> 2 blocks (16 warps)/SM to hide barrier+prefetch bubbles.
// ---------------------------------------------------------------------------
__global__ __launch_bounds__(256, 2) void leg_gemm(const float* __restrict__ w,
                                                   float* __restrict__ outf,
                                                   unsigned capF) {
    unsigned m   = blockIdx.z;
    unsigned l0  = blockIdx.x << 7;
    unsigned bc0 = blockIdx.y << 7;
    unsigned tid = threadIdx.x;
    unsigned tx = tid & 15u, ty = tid >> 4;

    float acc[8][8];
#pragma unroll
    for (int i = 0; i < 8; i++)
#pragma unroll
        for (int j = 0; j < 8; j++) acc[i][j] = 0.f;

    if (m <= l0 + 127u) {
        __shared__ __align__(16) float Ae[16][128];
        __shared__ __align__(16) float Ao[16][128];
        __shared__ __align__(16) float Bw[16][128];

        unsigned kk = tid >> 4;
        unsigned b4 = (tid & 15u) << 2;
        unsigned lw = tid >> 1;
        unsigned kw = (tid & 1u) << 3;
        bool lvalid = (l0 + lw) < LMAX;

        const float* Xm = g_X2 + (size_t)m * NROWS;
        const float* wL = w + (size_t)m * (LMAX * NLAT) + (size_t)(l0 + lw) * NLAT;

        const float (*Aev)[128] = (m & 1u) ? Ao : Ae;
        const float (*Aod)[128] = (m & 1u) ? Ae : Ao;

        float4 z4 = make_float4(0.f, 0.f, 0.f, 0.f);
        float4 fv0 = z4, fv1 = z4, rv0 = z4, rv1 = z4, wa = z4, wb = z4;
        if (kk < 180u) {
            const float* pf = Xm + (size_t)kk * NB + bc0 + b4;
            const float* pr = Xm + (size_t)(359u - kk) * NB + bc0 + b4;
            fv0 = *(const float4*)pf;       fv1 = *(const float4*)(pf + 64);
            rv0 = *(const float4*)pr;       rv1 = *(const float4*)(pr + 64);
        }
        if (lvalid) {
            wa = *(const float4*)(wL + kw);
            wb = *(const float4*)(wL + kw + 4);
        }

        for (unsigned k0 = 0; k0 < KBF; k0 += 16) {
            __syncthreads();
            {
                float4 e0 = make_float4(fv0.x + rv0.x, fv0.y + rv0.y, fv0.z + rv0.z, fv0.w + rv0.w);
                float4 e1 = make_float4(fv1.x + rv1.x, fv1.y + rv1.y, fv1.z + rv1.z, fv1.w + rv1.w);
                float4 o0 = make_float4(fv0.x - rv0.x, fv0.y - rv0.y, fv0.z - rv0.z, fv0.w - rv0.w);
                float4 o1 = make_float4(fv1.x - rv1.x, fv1.y - rv1.y, fv1.z - rv1.z, fv1.w - rv1.w);
                *(float4*)&Ae[kk][b4]      = e0;
                *(float4*)&Ae[kk][b4 + 64] = e1;
                *(float4*)&Ao[kk][b4]      = o0;
                *(float4*)&Ao[kk][b4 + 64] = o1;
            }
            Bw[kw + 0][lw] = wa.x; Bw[kw + 1][lw] = wa.y;
            Bw[kw + 2][lw] = wa.z; Bw[kw + 3][lw] = wa.w;
            Bw[kw + 4][lw] = wb.x; Bw[kw + 5][lw] = wb.y;
            Bw[kw + 6][lw] = wb.z; Bw[kw + 7][lw] = wb.w;
            __syncthreads();

            if (k0 + 16 < KBF) {
                unsigned kg = k0 + 16 + kk;
                fv0 = z4; fv1 = z4; rv0 = z4; rv1 = z4; wa = z4; wb = z4;
                if (kg < 180u) {
                    const float* pf = Xm + (size_t)kg * NB + bc0 + b4;
                    const float* pr = Xm + (size_t)(359u - kg) * NB + bc0 + b4;
                    fv0 = *(const float4*)pf;   fv1 = *(const float4*)(pf + 64);
                    rv0 = *(const float4*)pr;   rv1 = *(const float4*)(pr + 64);
                }
                if (lvalid) {
                    wa = *(const float4*)(wL + k0 + 16 + kw);
                    wb = *(const float4*)(wL + k0 + 16 + kw + 4);
                }
            }

#pragma unroll
            for (unsigned k = 0; k < 16; k++) {
                float4 e0 = *(const float4*)&Aev[k][tx << 2];
                float4 e1 = *(const float4*)&Aev[k][64 + (tx << 2)];
                float4 o0 = *(const float4*)&Aod[k][tx << 2];
                float4 o1 = *(const float4*)&Aod[k][64 + (tx << 2)];
                float4 c0 = *(const float4*)&Bw[k][ty << 2];
                float4 c1 = *(const float4*)&Bw[k][64 + (ty << 2)];
                float ee[8] = {e0.x, e0.y, e0.z, e0.w, e1.x, e1.y, e1.z, e1.w};
                float oo[8] = {o0.x, o0.y, o0.z, o0.w, o1.x, o1.y, o1.z, o1.w};
#pragma unroll
                for (int i = 0; i < 8; i++) {
                    acc[i][0] += ee[i] * c0.x;
                    acc[i][1] += oo[i] * c0.y;
                    acc[i][2] += ee[i] * c0.z;
                    acc[i][3] += oo[i] * c0.w;
                    acc[i][4] += ee[i] * c1.x;
                    acc[i][5] += oo[i] * c1.y;
                    acc[i][6] += ee[i] * c1.z;
                    acc[i][7] += oo[i] * c1.w;
                }
            }
        }
    }

#pragma unroll
    for (unsigned ih = 0; ih < 2; ih++)
#pragma unroll
        for (unsigned i = 0; i < 4; i++) {
            unsigned bc = bc0 + ih * 64u + (tx << 2) + i;
#pragma unroll
            for (unsigned jh = 0; jh < 2; jh++)
#pragma unroll
                for (unsigned j = 0; j < 4; j++) {
                    unsigned l = l0 + jh * 64u + (ty << 2) + j;
                    if (l < LMAX) {
                        unsigned oi = (bc * LMAX + l) * MMAX + m;
                        if (oi < capF) outf[oi] = acc[ih * 4 + i][jh * 4 + j];
                    }
                }
        }
}

// ---------------------------------------------------------------------------
extern "C" void kernel_launch(void* const* d_in, const int* in_sizes, int n_in,
                              void* d_out, int out_size) {
    const float* x = nullptr;
    const float* w = nullptr;
    for (int i = 0; i < n_in; i++) {
        long s = in_sizes[i];
        if (s == (long)X_ELEMS || s == (long)X_ELEMS * 4) x = (const float*)d_in[i];
        else if (s == (long)W_ELEMS || s == (long)W_ELEMS * 4) w = (const float*)d_in[i];
    }
    float* outf = (float*)d_out;

    long cf = (long)out_size;
    if (cf < 0) cf = 0;
    if (cf > (long)OUT_ELEMS) cf = (long)OUT_ELEMS;
    unsigned capF = (unsigned)cf;

    if (!x || !w) {
        zero_out<<<(capF + 255) / 256, 256>>>(outf, capF);
        return;
    }

    init_tables<<<(KF2 * FPAD + 255) / 256, 256>>>();

    fold_x<<<NROWS, 256>>>(x);                      // 92160 blocks

    dim3 gA(3, NROWS / 128);                        // 3 x 720
    dft_gemm<<<gA, 256>>>();

    dim3 gB(3, NB / 128, MMAX);                     // 3 x 2 x 361
    leg_gemm<<<gB, 256>>>(w, outf, capF);
}